// round 15
// baseline (speedup 1.0000x reference)
#include <cuda_runtime.h>
#include <cuda_fp16.h>

#define NN 100000
#define NE 1250000
#define D  64
#define EF 13
#define SCAN_B 1024

#define FMA2(d, a, b) \
    asm("fma.rn.f32x2 %0, %1, %2, %0;" : "+l"(d) : "l"(a), "l"(b))

// ------------- scratch (device globals; zero-init at load; self-cleaning) --------
__device__ int   g_bar;           // grid-barrier counter (reset by k_out)
__device__ int   g_rows[NE];
__device__ int   g_cols[NE];
__device__ float g_ew[NE];
__device__ float g_deg[NN];       // zero at kernel entry (self-cleaned by scanbuild)
__device__ int   g_cnt[NN];       // zero at kernel entry (self-cleaned by scanbuild)
__device__ float g_dinv[NN];
__device__ float g_dsq[NN];
__device__ int2  g_sc[NN];        // packed (start, cnt incl self-loop)
__device__ int   g_cursor[NN];
__device__ int   g_bsum[128];
__device__ __align__(16) uint2 g_edge[NE + NN];  // (row, norm); self loop first
__device__ __align__(16) __half g_hh[NN * D];    // GEMM output fp16 (gather payload)
__device__ __align__(16) float g_bufA[NN * D];   // x1
__device__ __align__(16) float g_bufB[NN * D];   // x2
__device__ float g_S[3 * D];      // zero at entry (self-cleaned by k_out)
__device__ float g_Z[3];          // zero at entry (self-cleaned by k_out)

// ---- launch 1: decode edge_index + edge weight + deg/cnt atomics ----------------
// softmax + dtype sniff computed per-block (cheap, avoids a separate init kernel).
// g_deg/g_cnt are zero on entry (module load or self-clean from previous replay).
__global__ void k_edges(const void* __restrict__ ei,
                        const float* __restrict__ ea,
                        const float* __restrict__ aaaaa, int E) {
    __shared__ float ssm[EF];
    __shared__ int sis64;
    if (threadIdx.x == 0) {
        const int* raw = (const int*)ei;
        int is64 = 1;
        for (int k = 0; k < 64; k++)
            if (raw[2 * k + 1] != 0) { is64 = 0; break; }
        sis64 = is64;
        float v[EF];
        float m = -1e30f;
        for (int j = 0; j < EF; j++) { v[j] = aaaaa[j]; m = fmaxf(m, v[j]); }
        float s = 0.0f;
        for (int j = 0; j < EF; j++) { v[j] = expf(v[j] - m); s += v[j]; }
        for (int j = 0; j < EF; j++) ssm[j] = v[j] / s;
    }
    __syncthreads();

    int e = blockIdx.x * blockDim.x + threadIdx.x;
    if (e >= E) return;
    int r, c;
    if (sis64) {
        const long long* p = (const long long*)ei;
        r = (int)p[e];
        c = (int)p[E + e];
    } else {
        const int* p = (const int*)ei;
        r = p[e];
        c = p[E + e];
    }
    g_rows[e] = r;
    g_cols[e] = c;

    const float* row = ea + (long long)e * EF;
    float s = 0.0f;
#pragma unroll
    for (int j = 0; j < EF; j++) s += __ldg(row + j) * ssm[j];
    g_ew[e] = s;
    atomicAdd(&g_deg[c], s);
    atomicAdd(&g_cnt[c], 1);
}

// ---- grid barrier (all blocks resident: nblk <= #SMs guaranteed by launch) ------
__device__ __forceinline__ void grid_barrier(int target) {
    __syncthreads();
    if (threadIdx.x == 0) {
        __threadfence();
        atomicAdd(&g_bar, 1);
        while (atomicAdd(&g_bar, 0) < target) { }
    }
    __syncthreads();
}

// ---- launch 2: dinv/dsq + block sums + global scan + self-loop + CSR build ------
// Single kernel, 98 blocks x 1024 threads, 2 internal grid barriers.
// Self-cleans g_deg/g_cnt for the next graph replay.
__global__ void __launch_bounds__(SCAN_B) k_scanbuild(int n, int nblk, int E) {
    __shared__ int sm[SCAN_B];
    __shared__ int sboff;
    int i = blockIdx.x * SCAN_B + threadIdx.x;

    // ---- phase 1: deg -> dinv/dsq (self-loop +1 folded in); block sum of cnt ----
    float di = 0.f, dsq = 0.f;
    int v = 0;
    if (i < n) {
        di = rsqrtf(1.0f + g_deg[i]);
        g_dinv[i] = di;
        dsq = di * di;
        g_dsq[i] = dsq;
        g_deg[i] = 0.0f;          // self-clean for next replay
        v = g_cnt[i] + 1;         // +1: self loop gets a CSR record
        g_cnt[i] = 0;             // self-clean for next replay
    }
    sm[threadIdx.x] = v;
    __syncthreads();
    for (int off = SCAN_B / 2; off > 0; off >>= 1) {
        if (threadIdx.x < off) sm[threadIdx.x] += sm[threadIdx.x + off];
        __syncthreads();
    }
    if (threadIdx.x == 0) g_bsum[blockIdx.x] = sm[0];

    grid_barrier(nblk);

    // ---- phase 2: block offset + in-block inclusive scan -> starts, cursors -----
    int partial = (threadIdx.x < blockIdx.x && threadIdx.x < nblk)
                  ? g_bsum[threadIdx.x] : 0;
    sm[threadIdx.x] = partial;
    __syncthreads();
    for (int off = SCAN_B / 2; off > 0; off >>= 1) {
        if (threadIdx.x < off) sm[threadIdx.x] += sm[threadIdx.x + off];
        __syncthreads();
    }
    if (threadIdx.x == 0) sboff = sm[0];
    __syncthreads();

    sm[threadIdx.x] = v;
    __syncthreads();
    for (int off = 1; off < SCAN_B; off <<= 1) {
        int t = (threadIdx.x >= off) ? sm[threadIdx.x - off] : 0;
        __syncthreads();
        sm[threadIdx.x] += t;
        __syncthreads();
    }
    if (i < n) {
        int st = sboff + sm[threadIdx.x] - v;   // exclusive
        g_sc[i] = make_int2(st, v);
        g_edge[st] = make_uint2((unsigned)i, __float_as_uint(dsq));  // self loop
        g_cursor[i] = st + 1;
    }

    grid_barrier(2 * nblk);

    // ---- phase 3: CSR build, grid-stride over edges ------------------------------
    int nthreads = nblk * SCAN_B;
    for (int e = blockIdx.x * SCAN_B + threadIdx.x; e < E; e += nthreads) {
        int r = g_rows[e];
        int c = g_cols[e];
        float nrm = g_dinv[r] * g_ew[e] * g_dinv[c];
        int pos = atomicAdd(&g_cursor[c], 1);
        g_edge[pos] = make_uint2((unsigned)r, __float_as_uint(nrm));
    }
}

// --- GEMM: h = x @ W (thread per row, W in smem, packed f32x2 FMA, full unroll) ---
__global__ void k_gemm(const float* __restrict__ xext, int sel,
                       const float* __restrict__ W, int n) {
    __shared__ __align__(16) float Ws[D * D];
    for (int i = threadIdx.x; i < D * D; i += blockDim.x) Ws[i] = W[i];
    __syncthreads();

    const float* x = (sel == 0) ? xext : ((sel == 1) ? g_bufA : g_bufB);
    int row = blockIdx.x * blockDim.x + threadIdx.x;
    if (row >= n) return;

    const float4* xr = (const float4*)(x + (long long)row * D);
    float4 xv[16];
#pragma unroll
    for (int k4 = 0; k4 < 16; k4++) xv[k4] = xr[k4];

    unsigned long long acc[32];   // 32 packed f32x2 = 64 output cols
#pragma unroll
    for (int c = 0; c < 32; c++) acc[c] = 0ull;

#pragma unroll
    for (int k4 = 0; k4 < 16; k4++) {
        float xa[4] = {xv[k4].x, xv[k4].y, xv[k4].z, xv[k4].w};
#pragma unroll
        for (int kk = 0; kk < 4; kk++) {
            unsigned long long xkk;
            asm("mov.b64 %0, {%1, %1};" : "=l"(xkk) : "f"(xa[kk]));
            const ulonglong2* w4 = (const ulonglong2*)&Ws[(k4 * 4 + kk) * D];
#pragma unroll
            for (int c2 = 0; c2 < 16; c2++) {
                ulonglong2 wv = w4[c2];
                FMA2(acc[2 * c2],     xkk, wv.x);
                FMA2(acc[2 * c2 + 1], xkk, wv.y);
            }
        }
    }
    __half2* ho = (__half2*)(g_hh + (long long)row * D);
#pragma unroll
    for (int c = 0; c < 32; c++) {
        float lo, hi;
        asm("mov.b64 {%0, %1}, %2;" : "=f"(lo), "=f"(hi) : "l"(acc[c]));
        ho[c] = __float22half2_rn(make_float2(lo, hi));
    }
}

// ------ fused CSR aggregate (self loop is a record) + bias/relu + pool ------------
// warp per node (grid-stride, single-wave grid); lane owns features (2l, 2l+1).
__global__ void __launch_bounds__(256) k_aggpool(
        int sel_out, const float* __restrict__ b,
        const float* __restrict__ wg, const float* __restrict__ bg,
        int layer, int n) {
    __shared__ float ps0[8][32];
    __shared__ float ps1[8][32];
    __shared__ float pz[8];
    float* xo = (sel_out == 1) ? g_bufA : ((sel_out == 2) ? g_bufB : 0);
    int lane = threadIdx.x & 31;
    int wlocal = threadIdx.x >> 5;
    int warp = (blockIdx.x * blockDim.x + threadIdx.x) >> 5;
    int nwarps = (gridDim.x * blockDim.x) >> 5;

    float wg0 = wg[2 * lane], wg1 = wg[2 * lane + 1];
    float b0 = b[2 * lane],  b1 = b[2 * lane + 1];
    float bgv = bg[0];

    const __half2* hp = (const __half2*)g_hh;   // element index = row*32 + lane

    float s0 = 0.f, s1 = 0.f, z = 0.f;

    for (int i = warp; i < n; i += nwarps) {
        int2 sc = __ldg(&g_sc[i]);       // (start, cnt) in one 8B load
        int j0 = sc.x;
        int cnt = sc.y;
        float a0 = 0.f, a1 = 0.f;

        for (int base = 0; base < cnt; base += 32) {
            int m = min(32, cnt - base);
            uint2 rec = make_uint2(0u, 0u);
            if (lane < m) rec = __ldg(&g_edge[j0 + base + lane]);

            int t = 0;
            for (; t + 1 < m; t += 2) {
                unsigned rx0 = __shfl_sync(0xffffffffu, rec.x, t);
                unsigned ry0 = __shfl_sync(0xffffffffu, rec.y, t);
                unsigned rx1 = __shfl_sync(0xffffffffu, rec.x, t + 1);
                unsigned ry1 = __shfl_sync(0xffffffffu, rec.y, t + 1);
                float2 f0 = __half22float2(hp[(long long)rx0 * 32 + lane]);
                float2 f1 = __half22float2(hp[(long long)rx1 * 32 + lane]);
                float n0 = __uint_as_float(ry0);
                float n1 = __uint_as_float(ry1);
                a0 = fmaf(n0, f0.x, a0); a1 = fmaf(n0, f0.y, a1);
                a0 = fmaf(n1, f1.x, a0); a1 = fmaf(n1, f1.y, a1);
            }
            if (t < m) {
                unsigned rx0 = __shfl_sync(0xffffffffu, rec.x, t);
                unsigned ry0 = __shfl_sync(0xffffffffu, rec.y, t);
                float2 f0 = __half22float2(hp[(long long)rx0 * 32 + lane]);
                float n0 = __uint_as_float(ry0);
                a0 = fmaf(n0, f0.x, a0); a1 = fmaf(n0, f0.y, a1);
            }
        }

        float v0 = fmaxf(a0 + b0, 0.f);
        float v1 = fmaxf(a1 + b1, 0.f);
        if (xo) {
            ((float2*)(xo + (long long)i * D))[lane] = make_float2(v0, v1);
        }

        float dot = v0 * wg0 + v1 * wg1;
#pragma unroll
        for (int off = 16; off > 0; off >>= 1)
            dot += __shfl_xor_sync(0xffffffffu, dot, off);
        float sg = 1.0f / (1.0f + expf(-(dot + bgv)));  // sigmoid gate
        float w = expf(sg);                             // softmax numerator
        s0 += w * v0;
        s1 += w * v1;
        if (lane == 0) z += w;
    }

    ps0[wlocal][lane] = s0;
    ps1[wlocal][lane] = s1;
    if (lane == 0) pz[wlocal] = z;
    __syncthreads();
    if (wlocal == 0) {
        float t0 = 0.f, t1 = 0.f, tz = 0.f;
#pragma unroll
        for (int w8 = 0; w8 < 8; w8++) {
            t0 += ps0[w8][lane];
            t1 += ps1[w8][lane];
            if (lane == 0) tz += pz[w8];
        }
        atomicAdd(&g_S[layer * D + 2 * lane], t0);
        atomicAdd(&g_S[layer * D + 2 * lane + 1], t1);
        if (lane == 0) atomicAdd(&g_Z[layer], tz);
    }
}

// -------- final divide; self-cleans pool accumulators + barrier for next replay ---
__global__ void k_out(float* __restrict__ out) {
    int t = threadIdx.x;
    float v = 0.f;
    if (t < 3 * D) v = g_S[t] / g_Z[t / D];
    __syncthreads();
    if (t < 3 * D) { out[t] = v; g_S[t] = 0.f; }
    if (t < 3) g_Z[t] = 0.f;
    if (t == 0) g_bar = 0;
}

// ---------------- launch ----------------------------------------------------------
extern "C" void kernel_launch(void* const* d_in, const int* in_sizes, int n_in,
                              void* d_out, int out_size) {
    const float* x     = (const float*)d_in[0];
    const void*  ei    = d_in[1];
    const float* ea    = (const float*)d_in[2];
    const float* aaaaa = (const float*)d_in[3];
    const float* W[3]  = {(const float*)d_in[4], (const float*)d_in[6], (const float*)d_in[8]};
    const float* b[3]  = {(const float*)d_in[5], (const float*)d_in[7], (const float*)d_in[9]};
    const float* wg[3] = {(const float*)d_in[10], (const float*)d_in[12], (const float*)d_in[14]};
    const float* bg[3] = {(const float*)d_in[11], (const float*)d_in[13], (const float*)d_in[15]};
    float* out = (float*)d_out;

    int N = in_sizes[0] / D;     // 100000
    int E = in_sizes[2] / EF;    // 1250000
    int nblk = (N + SCAN_B - 1) / SCAN_B;   // 98 blocks <= 148 SMs: all resident

    // launch 1 + 2: preprocessing
    k_edges<<<(E + 255) / 256, 256>>>(ei, ea, aaaaa, E);
    k_scanbuild<<<nblk, SCAN_B>>>(N, nblk, E);

    const int AGG_BLOCKS = 740;   // 148 SMs x 5 blocks: single wave
    // layer 1 (launches 3,4 -- aggpool is the 4th launch => ncu capture target)
    k_gemm<<<(N + 127) / 128, 128>>>(x, 0, W[0], N);
    k_aggpool<<<AGG_BLOCKS, 256>>>(1, b[0], wg[0], bg[0], 0, N);
    // layer 2
    k_gemm<<<(N + 127) / 128, 128>>>(x, 1, W[1], N);
    k_aggpool<<<AGG_BLOCKS, 256>>>(2, b[1], wg[1], bg[1], 1, N);
    // layer 3 (pool only)
    k_gemm<<<(N + 127) / 128, 128>>>(x, 2, W[2], N);
    k_aggpool<<<AGG_BLOCKS, 256>>>(0, b[2], wg[2], bg[2], 2, N);

    k_out<<<1, 192>>>(out);
}

// round 16
// speedup vs baseline: 1.0499x; 1.0499x over previous
#include <cuda_runtime.h>
#include <cuda_fp16.h>

#define NN 100000
#define NE 1250000
#define D  64
#define EF 13
#define SCAN_B 1024

#define FMA2(d, a, b) \
    asm("fma.rn.f32x2 %0, %1, %2, %0;" : "+l"(d) : "l"(a), "l"(b))

// ------------- scratch (device globals; zero-init at load; self-cleaning) --------
__device__ int   g_bar;           // grid-barrier counter (reset by k_out)
__device__ int   g_rows[NE];
__device__ int   g_cols[NE];
__device__ float g_ew[NE];
__device__ float g_deg[NN];       // zero at kernel entry (self-cleaned by scanbuild)
__device__ int   g_cnt[NN];       // zero at kernel entry (self-cleaned by scanbuild)
__device__ float g_dinv[NN];
__device__ int2  g_sc[NN];        // packed (start, cnt incl self-loop)
__device__ int   g_cursor[NN];
__device__ int   g_bsum[128];
__device__ __align__(16) uint2 g_edge[NE + NN];  // (row, norm as dup half2)
__device__ __align__(16) __half g_hh[NN * D];    // GEMM output fp16 (gather payload)
__device__ __align__(16) float g_bufA[NN * D];   // x1
__device__ __align__(16) float g_bufB[NN * D];   // x2
__device__ float g_S[3 * D];      // zero at entry (self-cleaned by k_out)
__device__ float g_Z[3];          // zero at entry (self-cleaned by k_out)

// ---- launch 1: decode edge_index + edge weight + deg/cnt atomics ----------------
__global__ void k_edges(const void* __restrict__ ei,
                        const float* __restrict__ ea,
                        const float* __restrict__ aaaaa, int E) {
    __shared__ float ssm[EF];
    __shared__ int sis64;
    if (threadIdx.x == 0) {
        const int* raw = (const int*)ei;
        int is64 = 1;
        for (int k = 0; k < 64; k++)
            if (raw[2 * k + 1] != 0) { is64 = 0; break; }
        sis64 = is64;
        float v[EF];
        float m = -1e30f;
        for (int j = 0; j < EF; j++) { v[j] = aaaaa[j]; m = fmaxf(m, v[j]); }
        float s = 0.0f;
        for (int j = 0; j < EF; j++) { v[j] = expf(v[j] - m); s += v[j]; }
        for (int j = 0; j < EF; j++) ssm[j] = v[j] / s;
    }
    __syncthreads();

    int e = blockIdx.x * blockDim.x + threadIdx.x;
    if (e >= E) return;
    int r, c;
    if (sis64) {
        const long long* p = (const long long*)ei;
        r = (int)p[e];
        c = (int)p[E + e];
    } else {
        const int* p = (const int*)ei;
        r = p[e];
        c = p[E + e];
    }
    g_rows[e] = r;
    g_cols[e] = c;

    const float* row = ea + (long long)e * EF;
    float s = 0.0f;
#pragma unroll
    for (int j = 0; j < EF; j++) s += __ldg(row + j) * ssm[j];
    g_ew[e] = s;
    atomicAdd(&g_deg[c], s);
    atomicAdd(&g_cnt[c], 1);
}

// ---- grid barrier (all blocks resident: nblk <= #SMs guaranteed by launch) ------
__device__ __forceinline__ void grid_barrier(int target) {
    __syncthreads();
    if (threadIdx.x == 0) {
        __threadfence();
        atomicAdd(&g_bar, 1);
        while (atomicAdd(&g_bar, 0) < target) { }
    }
    __syncthreads();
}

// ---- launch 2: dinv/dsq + scan + self-loop + CSR build (norm packed as half2) ----
__global__ void __launch_bounds__(SCAN_B) k_scanbuild(int n, int nblk, int E) {
    __shared__ int sm[SCAN_B];
    __shared__ int sboff;
    int i = blockIdx.x * SCAN_B + threadIdx.x;

    // ---- phase 1: deg -> dinv (self-loop +1 folded in); block sum of cnt --------
    float di = 0.f, dsq = 0.f;
    int v = 0;
    if (i < n) {
        di = rsqrtf(1.0f + g_deg[i]);
        g_dinv[i] = di;
        dsq = di * di;
        g_deg[i] = 0.0f;          // self-clean for next replay
        v = g_cnt[i] + 1;         // +1: self loop gets a CSR record
        g_cnt[i] = 0;             // self-clean for next replay
    }
    sm[threadIdx.x] = v;
    __syncthreads();
    for (int off = SCAN_B / 2; off > 0; off >>= 1) {
        if (threadIdx.x < off) sm[threadIdx.x] += sm[threadIdx.x + off];
        __syncthreads();
    }
    if (threadIdx.x == 0) g_bsum[blockIdx.x] = sm[0];

    grid_barrier(nblk);

    // ---- phase 2: block offset + in-block inclusive scan -> starts, cursors -----
    int partial = (threadIdx.x < blockIdx.x && threadIdx.x < nblk)
                  ? g_bsum[threadIdx.x] : 0;
    sm[threadIdx.x] = partial;
    __syncthreads();
    for (int off = SCAN_B / 2; off > 0; off >>= 1) {
        if (threadIdx.x < off) sm[threadIdx.x] += sm[threadIdx.x + off];
        __syncthreads();
    }
    if (threadIdx.x == 0) sboff = sm[0];
    __syncthreads();

    sm[threadIdx.x] = v;
    __syncthreads();
    for (int off = 1; off < SCAN_B; off <<= 1) {
        int t = (threadIdx.x >= off) ? sm[threadIdx.x - off] : 0;
        __syncthreads();
        sm[threadIdx.x] += t;
        __syncthreads();
    }
    if (i < n) {
        int st = sboff + sm[threadIdx.x] - v;   // exclusive
        g_sc[i] = make_int2(st, v);
        __half2 dh = __float2half2_rn(dsq);
        g_edge[st] = make_uint2((unsigned)i, *(unsigned*)&dh);  // self loop
        g_cursor[i] = st + 1;
    }

    grid_barrier(2 * nblk);

    // ---- phase 3: CSR build, grid-stride over edges ------------------------------
    int nthreads = nblk * SCAN_B;
    for (int e = blockIdx.x * SCAN_B + threadIdx.x; e < E; e += nthreads) {
        int r = g_rows[e];
        int c = g_cols[e];
        float nrm = g_dinv[r] * g_ew[e] * g_dinv[c];
        int pos = atomicAdd(&g_cursor[c], 1);
        __half2 nh = __float2half2_rn(nrm);
        g_edge[pos] = make_uint2((unsigned)r, *(unsigned*)&nh);
    }
}

// --- GEMM: h = x @ W (thread per row, W in smem, packed f32x2 FMA, full unroll) ---
__global__ void k_gemm(const float* __restrict__ xext, int sel,
                       const float* __restrict__ W, int n) {
    __shared__ __align__(16) float Ws[D * D];
    for (int i = threadIdx.x; i < D * D; i += blockDim.x) Ws[i] = W[i];
    __syncthreads();

    const float* x = (sel == 0) ? xext : ((sel == 1) ? g_bufA : g_bufB);
    int row = blockIdx.x * blockDim.x + threadIdx.x;
    if (row >= n) return;

    const float4* xr = (const float4*)(x + (long long)row * D);
    float4 xv[16];
#pragma unroll
    for (int k4 = 0; k4 < 16; k4++) xv[k4] = xr[k4];

    unsigned long long acc[32];   // 32 packed f32x2 = 64 output cols
#pragma unroll
    for (int c = 0; c < 32; c++) acc[c] = 0ull;

#pragma unroll
    for (int k4 = 0; k4 < 16; k4++) {
        float xa[4] = {xv[k4].x, xv[k4].y, xv[k4].z, xv[k4].w};
#pragma unroll
        for (int kk = 0; kk < 4; kk++) {
            unsigned long long xkk;
            asm("mov.b64 %0, {%1, %1};" : "=l"(xkk) : "f"(xa[kk]));
            const ulonglong2* w4 = (const ulonglong2*)&Ws[(k4 * 4 + kk) * D];
#pragma unroll
            for (int c2 = 0; c2 < 16; c2++) {
                ulonglong2 wv = w4[c2];
                FMA2(acc[2 * c2],     xkk, wv.x);
                FMA2(acc[2 * c2 + 1], xkk, wv.y);
            }
        }
    }
    __half2* ho = (__half2*)(g_hh + (long long)row * D);
#pragma unroll
    for (int c = 0; c < 32; c++) {
        float lo, hi;
        asm("mov.b64 {%0, %1}, %2;" : "=f"(lo), "=f"(hi) : "l"(acc[c]));
        ho[c] = __float22half2_rn(make_float2(lo, hi));
    }
}

// ------ fused CSR aggregate + bias/relu + pool -------------------------------------
// Warp per node; 4 edges per iteration, 8 lanes per edge (lane = 8*g + k):
//   lane loads uint4 = 4 half2 = features 8k..8k+7 of its edge's source row.
// Per 4 edges: 2 SHFL + 2 addr + 1 LDG.128 + 4 HFMA2  (~3 instr/edge).
// Epilogue per node: butterfly over lane bits 3..4 merges the 4 edge subgroups.
__global__ void __launch_bounds__(256) k_aggpool(
        int sel_out, const float* __restrict__ b,
        const float* __restrict__ wg, const float* __restrict__ bg,
        int layer, int n) {
    __shared__ float psum[8][64];
    __shared__ float pz[8];
    float* xo = (sel_out == 1) ? g_bufA : ((sel_out == 2) ? g_bufB : 0);
    int lane = threadIdx.x & 31;
    int k = lane & 7;          // feature octet: features 8k..8k+7
    int g = lane >> 3;         // edge subgroup 0..3
    int wlocal = threadIdx.x >> 5;
    int warp = (blockIdx.x * blockDim.x + threadIdx.x) >> 5;
    int nwarps = (gridDim.x * blockDim.x) >> 5;

    float bb[8], wgg[8];
#pragma unroll
    for (int j = 0; j < 8; j++) { bb[j] = b[8 * k + j]; wgg[j] = wg[8 * k + j]; }
    float bgv = bg[0];

    const uint4* hp4 = (const uint4*)g_hh;   // row = 8 uint4; lane reads row*8+k

    float s[8];
#pragma unroll
    for (int j = 0; j < 8; j++) s[j] = 0.f;
    float z = 0.f;

    for (int i = warp; i < n; i += nwarps) {
        int2 sc = __ldg(&g_sc[i]);
        int j0 = sc.x;
        int cnt = sc.y;
        __half2 acc[4];
        acc[0] = acc[1] = acc[2] = acc[3] = __float2half2_rn(0.f);

        for (int base = 0; base < cnt; base += 32) {
            int m = min(32, cnt - base);
            // zero-records beyond m: row 0, norm 0 (harmless)
            uint2 rec = make_uint2(0u, 0u);
            if (lane < m) rec = __ldg(&g_edge[j0 + base + lane]);

            for (int t = 0; t < m; t += 4) {
                int src = t + g;   // t <= 28, g <= 3 -> src <= 31, never wraps
                unsigned rx  = __shfl_sync(0xffffffffu, rec.x, src);
                unsigned ryu = __shfl_sync(0xffffffffu, rec.y, src);
                __half2 nh = *(__half2*)&ryu;
                uint4 p = __ldg(&hp4[(long long)rx * 8 + k]);
                __half2* ph = (__half2*)&p;
                acc[0] = __hfma2(nh, ph[0], acc[0]);
                acc[1] = __hfma2(nh, ph[1], acc[1]);
                acc[2] = __hfma2(nh, ph[2], acc[2]);
                acc[3] = __hfma2(nh, ph[3], acc[3]);
            }
        }

        // merge the 4 edge subgroups (lane bits 3 and 4)
#pragma unroll
        for (int off = 8; off <= 16; off <<= 1) {
#pragma unroll
            for (int j = 0; j < 4; j++) {
                unsigned u = *(unsigned*)&acc[j];
                unsigned o = __shfl_xor_sync(0xffffffffu, u, off);
                acc[j] = __hadd2(acc[j], *(__half2*)&o);
            }
        }

        // bias + relu in fp32
        float v[8];
#pragma unroll
        for (int j = 0; j < 4; j++) {
            float2 f2 = __half22float2(acc[j]);
            v[2 * j]     = fmaxf(f2.x + bb[2 * j],     0.f);
            v[2 * j + 1] = fmaxf(f2.y + bb[2 * j + 1], 0.f);
        }

        if (xo) {
            float* xrow = xo + (long long)i * D + 8 * k;
            if (g == 0)      *(float4*)xrow       = make_float4(v[0], v[1], v[2], v[3]);
            else if (g == 1) *(float4*)(xrow + 4) = make_float4(v[4], v[5], v[6], v[7]);
        }

        // attention pool: dot over this lane's 8 features, reduce over k (bits 0-2)
        float dot = 0.f;
#pragma unroll
        for (int j = 0; j < 8; j++) dot = fmaf(v[j], wgg[j], dot);
        dot += __shfl_xor_sync(0xffffffffu, dot, 1);
        dot += __shfl_xor_sync(0xffffffffu, dot, 2);
        dot += __shfl_xor_sync(0xffffffffu, dot, 4);
        float sg = 1.0f / (1.0f + expf(-(dot + bgv)));  // sigmoid gate
        float w = expf(sg);                             // softmax numerator
#pragma unroll
        for (int j = 0; j < 8; j++) s[j] = fmaf(w, v[j], s[j]);
        if (lane == 0) z += w;
    }

    // pool partials: lanes g==0 hold canonical copies
    if (g == 0) {
#pragma unroll
        for (int j = 0; j < 8; j++) psum[wlocal][8 * k + j] = s[j];
    }
    if (lane == 0) pz[wlocal] = z;
    __syncthreads();
    if (wlocal == 0) {
        float t0 = 0.f, t1 = 0.f, tz = 0.f;
#pragma unroll
        for (int w8 = 0; w8 < 8; w8++) {
            t0 += psum[w8][2 * lane];
            t1 += psum[w8][2 * lane + 1];
            if (lane == 0) tz += pz[w8];
        }
        atomicAdd(&g_S[layer * D + 2 * lane], t0);
        atomicAdd(&g_S[layer * D + 2 * lane + 1], t1);
        if (lane == 0) atomicAdd(&g_Z[layer], tz);
    }
}

// -------- final divide; self-cleans pool accumulators + barrier for next replay ---
__global__ void k_out(float* __restrict__ out) {
    int t = threadIdx.x;
    float v = 0.f;
    if (t < 3 * D) v = g_S[t] / g_Z[t / D];
    __syncthreads();
    if (t < 3 * D) { out[t] = v; g_S[t] = 0.f; }
    if (t < 3) g_Z[t] = 0.f;
    if (t == 0) g_bar = 0;
}

// ---------------- launch ----------------------------------------------------------
extern "C" void kernel_launch(void* const* d_in, const int* in_sizes, int n_in,
                              void* d_out, int out_size) {
    const float* x     = (const float*)d_in[0];
    const void*  ei    = d_in[1];
    const float* ea    = (const float*)d_in[2];
    const float* aaaaa = (const float*)d_in[3];
    const float* W[3]  = {(const float*)d_in[4], (const float*)d_in[6], (const float*)d_in[8]};
    const float* b[3]  = {(const float*)d_in[5], (const float*)d_in[7], (const float*)d_in[9]};
    const float* wg[3] = {(const float*)d_in[10], (const float*)d_in[12], (const float*)d_in[14]};
    const float* bg[3] = {(const float*)d_in[11], (const float*)d_in[13], (const float*)d_in[15]};
    float* out = (float*)d_out;

    int N = in_sizes[0] / D;     // 100000
    int E = in_sizes[2] / EF;    // 1250000
    int nblk = (N + SCAN_B - 1) / SCAN_B;   // 98 blocks <= 148 SMs: all resident

    k_edges<<<(E + 255) / 256, 256>>>(ei, ea, aaaaa, E);
    k_scanbuild<<<nblk, SCAN_B>>>(N, nblk, E);

    const int AGG_BLOCKS = 740;   // 148 SMs x 5 blocks: single wave
    // layer 1 (aggpool is launch #4 => ncu capture target)
    k_gemm<<<(N + 127) / 128, 128>>>(x, 0, W[0], N);
    k_aggpool<<<AGG_BLOCKS, 256>>>(1, b[0], wg[0], bg[0], 0, N);
    // layer 2
    k_gemm<<<(N + 127) / 128, 128>>>(x, 1, W[1], N);
    k_aggpool<<<AGG_BLOCKS, 256>>>(2, b[1], wg[1], bg[1], 1, N);
    // layer 3 (pool only)
    k_gemm<<<(N + 127) / 128, 128>>>(x, 2, W[2], N);
    k_aggpool<<<AGG_BLOCKS, 256>>>(0, b[2], wg[2], bg[2], 2, N);

    k_out<<<1, 192>>>(out);
}

// round 17
// speedup vs baseline: 1.0719x; 1.0210x over previous
#include <cuda_runtime.h>
#include <cuda_fp16.h>

#define NN 100000
#define NE 1250000
#define D  64
#define EF 13
#define SCAN_B 1024

#define FMA2(d, a, b) \
    asm("fma.rn.f32x2 %0, %1, %2, %0;" : "+l"(d) : "l"(a), "l"(b))

// ------------- scratch (device globals; zero-init at load; self-cleaning) --------
__device__ int   g_bar;           // grid-barrier counter (reset by k_out)
__device__ int   g_rows[NE];
__device__ int   g_cols[NE];
__device__ float g_ew[NE];
__device__ float g_deg[NN];       // zero at kernel entry (self-cleaned by scanbuild)
__device__ int   g_cnt[NN];       // zero at kernel entry (self-cleaned by scanbuild)
__device__ float g_dinv[NN];
__device__ int2  g_sc[NN];        // packed (start, cnt incl self-loop)
__device__ int   g_cursor[NN];
__device__ int   g_bsum[128];
__device__ __align__(16) uint2 g_edge[NE + NN];  // (row, norm as dup half2)
__device__ __align__(16) __half g_hh[NN * D];    // GEMM output fp16 (gather payload)
__device__ __align__(16) float g_bufA[NN * D];   // x1
__device__ __align__(16) float g_bufB[NN * D];   // x2
__device__ float g_S[3 * D];      // zero at entry (self-cleaned by k_out)
__device__ float g_Z[3];          // zero at entry (self-cleaned by k_out)

// ---- launch 1: decode edge_index + edge weight + deg/cnt atomics ----------------
__global__ void k_edges(const void* __restrict__ ei,
                        const float* __restrict__ ea,
                        const float* __restrict__ aaaaa, int E) {
    __shared__ float ssm[EF];
    __shared__ int sis64;
    if (threadIdx.x == 0) {
        const int* raw = (const int*)ei;
        int is64 = 1;
        for (int k = 0; k < 64; k++)
            if (raw[2 * k + 1] != 0) { is64 = 0; break; }
        sis64 = is64;
        float v[EF];
        float m = -1e30f;
        for (int j = 0; j < EF; j++) { v[j] = aaaaa[j]; m = fmaxf(m, v[j]); }
        float s = 0.0f;
        for (int j = 0; j < EF; j++) { v[j] = expf(v[j] - m); s += v[j]; }
        for (int j = 0; j < EF; j++) ssm[j] = v[j] / s;
    }
    __syncthreads();

    int e = blockIdx.x * blockDim.x + threadIdx.x;
    if (e >= E) return;
    int r, c;
    if (sis64) {
        const long long* p = (const long long*)ei;
        r = (int)p[e];
        c = (int)p[E + e];
    } else {
        const int* p = (const int*)ei;
        r = p[e];
        c = p[E + e];
    }
    g_rows[e] = r;
    g_cols[e] = c;

    const float* row = ea + (long long)e * EF;
    float s = 0.0f;
#pragma unroll
    for (int j = 0; j < EF; j++) s += __ldg(row + j) * ssm[j];
    g_ew[e] = s;
    atomicAdd(&g_deg[c], s);
    atomicAdd(&g_cnt[c], 1);
}

// ---- grid barrier (all blocks resident: nblk <= #SMs guaranteed by launch) ------
__device__ __forceinline__ void grid_barrier(int target) {
    __syncthreads();
    if (threadIdx.x == 0) {
        __threadfence();
        atomicAdd(&g_bar, 1);
        while (atomicAdd(&g_bar, 0) < target) { }
    }
    __syncthreads();
}

// ---- launch 2: dinv + scan + self-loop + CSR build (norm packed as dup half2) ----
__global__ void __launch_bounds__(SCAN_B) k_scanbuild(int n, int nblk, int E) {
    __shared__ int sm[SCAN_B];
    __shared__ int sboff;
    int i = blockIdx.x * SCAN_B + threadIdx.x;

    // ---- phase 1: deg -> dinv (self-loop +1 folded in); block sum of cnt --------
    float di = 0.f, dsq = 0.f;
    int v = 0;
    if (i < n) {
        di = rsqrtf(1.0f + g_deg[i]);
        g_dinv[i] = di;
        dsq = di * di;
        g_deg[i] = 0.0f;          // self-clean for next replay
        v = g_cnt[i] + 1;         // +1: self loop gets a CSR record
        g_cnt[i] = 0;             // self-clean for next replay
    }
    sm[threadIdx.x] = v;
    __syncthreads();
    for (int off = SCAN_B / 2; off > 0; off >>= 1) {
        if (threadIdx.x < off) sm[threadIdx.x] += sm[threadIdx.x + off];
        __syncthreads();
    }
    if (threadIdx.x == 0) g_bsum[blockIdx.x] = sm[0];

    grid_barrier(nblk);

    // ---- phase 2: block offset + in-block inclusive scan -> starts, cursors -----
    int partial = (threadIdx.x < blockIdx.x && threadIdx.x < nblk)
                  ? g_bsum[threadIdx.x] : 0;
    sm[threadIdx.x] = partial;
    __syncthreads();
    for (int off = SCAN_B / 2; off > 0; off >>= 1) {
        if (threadIdx.x < off) sm[threadIdx.x] += sm[threadIdx.x + off];
        __syncthreads();
    }
    if (threadIdx.x == 0) sboff = sm[0];
    __syncthreads();

    sm[threadIdx.x] = v;
    __syncthreads();
    for (int off = 1; off < SCAN_B; off <<= 1) {
        int t = (threadIdx.x >= off) ? sm[threadIdx.x - off] : 0;
        __syncthreads();
        sm[threadIdx.x] += t;
        __syncthreads();
    }
    if (i < n) {
        int st = sboff + sm[threadIdx.x] - v;   // exclusive
        g_sc[i] = make_int2(st, v);
        __half2 dh = __float2half2_rn(dsq);
        g_edge[st] = make_uint2((unsigned)i, *(unsigned*)&dh);  // self loop
        g_cursor[i] = st + 1;
    }

    grid_barrier(2 * nblk);

    // ---- phase 3: CSR build, grid-stride over edges ------------------------------
    int nthreads = nblk * SCAN_B;
    for (int e = blockIdx.x * SCAN_B + threadIdx.x; e < E; e += nthreads) {
        int r = g_rows[e];
        int c = g_cols[e];
        float nrm = g_dinv[r] * g_ew[e] * g_dinv[c];
        int pos = atomicAdd(&g_cursor[c], 1);
        __half2 nh = __float2half2_rn(nrm);
        g_edge[pos] = make_uint2((unsigned)r, *(unsigned*)&nh);
    }
}

// --- GEMM: h = x @ W (thread per row, W in smem, packed f32x2 FMA, full unroll) ---
__global__ void k_gemm(const float* __restrict__ xext, int sel,
                       const float* __restrict__ W, int n) {
    __shared__ __align__(16) float Ws[D * D];
    for (int i = threadIdx.x; i < D * D; i += blockDim.x) Ws[i] = W[i];
    __syncthreads();

    const float* x = (sel == 0) ? xext : ((sel == 1) ? g_bufA : g_bufB);
    int row = blockIdx.x * blockDim.x + threadIdx.x;
    if (row >= n) return;

    const float4* xr = (const float4*)(x + (long long)row * D);
    float4 xv[16];
#pragma unroll
    for (int k4 = 0; k4 < 16; k4++) xv[k4] = xr[k4];

    unsigned long long acc[32];   // 32 packed f32x2 = 64 output cols
#pragma unroll
    for (int c = 0; c < 32; c++) acc[c] = 0ull;

#pragma unroll
    for (int k4 = 0; k4 < 16; k4++) {
        float xa[4] = {xv[k4].x, xv[k4].y, xv[k4].z, xv[k4].w};
#pragma unroll
        for (int kk = 0; kk < 4; kk++) {
            unsigned long long xkk;
            asm("mov.b64 %0, {%1, %1};" : "=l"(xkk) : "f"(xa[kk]));
            const ulonglong2* w4 = (const ulonglong2*)&Ws[(k4 * 4 + kk) * D];
#pragma unroll
            for (int c2 = 0; c2 < 16; c2++) {
                ulonglong2 wv = w4[c2];
                FMA2(acc[2 * c2],     xkk, wv.x);
                FMA2(acc[2 * c2 + 1], xkk, wv.y);
            }
        }
    }
    __half2* ho = (__half2*)(g_hh + (long long)row * D);
#pragma unroll
    for (int c = 0; c < 32; c++) {
        float lo, hi;
        asm("mov.b64 {%0, %1}, %2;" : "=f"(lo), "=f"(hi) : "l"(acc[c]));
        ho[c] = __float22half2_rn(make_float2(lo, hi));
    }
}

// ------ fused CSR aggregate + bias/relu + pool -------------------------------------
// 4 nodes per warp, one node per 8-lane subgroup (lane = 8*g + k):
//   lane covers features 8k..8k+7 of node g; accumulator complete per subgroup
//   (NO cross-subgroup merge). Epilogue executes once per 4 nodes.
__global__ void __launch_bounds__(256) k_aggpool(
        int sel_out, const float* __restrict__ b,
        const float* __restrict__ wg, const float* __restrict__ bg,
        int layer, int n) {
    __shared__ float psum[8][64];
    __shared__ float pz[8];
    float* xo = (sel_out == 1) ? g_bufA : ((sel_out == 2) ? g_bufB : 0);
    int lane = threadIdx.x & 31;
    int k = lane & 7;          // feature octet within node
    int g = lane >> 3;         // node slot 0..3 within warp
    int wlocal = threadIdx.x >> 5;
    int warp = (blockIdx.x * blockDim.x + threadIdx.x) >> 5;
    int nwarps = (gridDim.x * blockDim.x) >> 5;
    const unsigned FULL = 0xffffffffu;

    float bb[8], wgg[8];
#pragma unroll
    for (int j = 0; j < 8; j++) { bb[j] = b[8 * k + j]; wgg[j] = wg[8 * k + j]; }
    float bgv = bg[0];

    const uint4* hp4 = (const uint4*)g_hh;   // row = 8 uint4; lane reads row*8+k

    float s[8];
#pragma unroll
    for (int j = 0; j < 8; j++) s[j] = 0.f;
    float z = 0.f;

    for (int i0 = warp * 4; i0 < n; i0 += nwarps * 4) {
        int i = i0 + g;                       // this subgroup's node
        bool active = (i < n);
        int2 sc = active ? __ldg(&g_sc[i]) : make_int2(0, 0);
        int j0 = sc.x;
        int cnt = sc.y;

        // warp-uniform loop bound: max cnt over the 4 subgroups
        int cmax = cnt;
        cmax = max(cmax, __shfl_xor_sync(FULL, cmax, 8));
        cmax = max(cmax, __shfl_xor_sync(FULL, cmax, 16));

        __half2 acc[4];
        acc[0] = acc[1] = acc[2] = acc[3] = __float2half2_rn(0.f);

        for (int base = 0; base < cmax; base += 8) {
            // each subgroup's 8 lanes fetch its node's next 8 records
            uint2 rec = make_uint2(0u, 0u);
            if (base + k < cnt) rec = __ldg(&g_edge[j0 + base + k]);

            int mm = min(8, cmax - base);
            for (int t = 0; t < mm; t++) {
                unsigned rx = __shfl_sync(FULL, rec.x, t, 8);   // within subgroup
                unsigned ry = __shfl_sync(FULL, rec.y, t, 8);
                __half2 nh = *(__half2*)&ry;
                uint4 p = __ldg(&hp4[(long long)rx * 8 + k]);
                __half2* ph = (__half2*)&p;
                acc[0] = __hfma2(nh, ph[0], acc[0]);
                acc[1] = __hfma2(nh, ph[1], acc[1]);
                acc[2] = __hfma2(nh, ph[2], acc[2]);
                acc[3] = __hfma2(nh, ph[3], acc[3]);
            }
        }

        // bias + relu in fp32 (4 nodes in parallel; no merge needed)
        float v[8];
#pragma unroll
        for (int j = 0; j < 4; j++) {
            float2 f2 = __half22float2(acc[j]);
            v[2 * j]     = fmaxf(f2.x + bb[2 * j],     0.f);
            v[2 * j + 1] = fmaxf(f2.y + bb[2 * j + 1], 0.f);
        }

        if (xo && active) {
            float* xrow = xo + (long long)i * D + 8 * k;
            *(float4*)xrow       = make_float4(v[0], v[1], v[2], v[3]);
            *(float4*)(xrow + 4) = make_float4(v[4], v[5], v[6], v[7]);
        }

        // attention pool: subgroup dot (reduce over k bits 0..2)
        float dot = 0.f;
#pragma unroll
        for (int j = 0; j < 8; j++) dot = fmaf(v[j], wgg[j], dot);
        dot += __shfl_xor_sync(FULL, dot, 1);
        dot += __shfl_xor_sync(FULL, dot, 2);
        dot += __shfl_xor_sync(FULL, dot, 4);
        float sg = 1.0f / (1.0f + expf(-(dot + bgv)));  // sigmoid gate
        float w = expf(sg);                             // softmax numerator
        if (!active) w = 0.f;                           // tail guard
#pragma unroll
        for (int j = 0; j < 8; j++) s[j] = fmaf(w, v[j], s[j]);
        if (k == 0) z += w;
    }

    // merge the 4 subgroup partials (once per kernel)
#pragma unroll
    for (int j = 0; j < 8; j++) {
        s[j] += __shfl_xor_sync(FULL, s[j], 8);
        s[j] += __shfl_xor_sync(FULL, s[j], 16);
    }
    z += __shfl_xor_sync(FULL, z, 8);
    z += __shfl_xor_sync(FULL, z, 16);

    if (g == 0) {
#pragma unroll
        for (int j = 0; j < 8; j++) psum[wlocal][8 * k + j] = s[j];
    }
    if (lane == 0) pz[wlocal] = z;
    __syncthreads();
    if (wlocal == 0) {
        float t0 = 0.f, t1 = 0.f, tz = 0.f;
#pragma unroll
        for (int w8 = 0; w8 < 8; w8++) {
            t0 += psum[w8][2 * lane];
            t1 += psum[w8][2 * lane + 1];
            if (lane == 0) tz += pz[w8];
        }
        atomicAdd(&g_S[layer * D + 2 * lane], t0);
        atomicAdd(&g_S[layer * D + 2 * lane + 1], t1);
        if (lane == 0) atomicAdd(&g_Z[layer], tz);
    }
}

// -------- final divide; self-cleans pool accumulators + barrier for next replay ---
__global__ void k_out(float* __restrict__ out) {
    int t = threadIdx.x;
    float v = 0.f;
    if (t < 3 * D) v = g_S[t] / g_Z[t / D];
    __syncthreads();
    if (t < 3 * D) { out[t] = v; g_S[t] = 0.f; }
    if (t < 3) g_Z[t] = 0.f;
    if (t == 0) g_bar = 0;
}

// ---------------- launch ----------------------------------------------------------
extern "C" void kernel_launch(void* const* d_in, const int* in_sizes, int n_in,
                              void* d_out, int out_size) {
    const float* x     = (const float*)d_in[0];
    const void*  ei    = d_in[1];
    const float* ea    = (const float*)d_in[2];
    const float* aaaaa = (const float*)d_in[3];
    const float* W[3]  = {(const float*)d_in[4], (const float*)d_in[6], (const float*)d_in[8]};
    const float* b[3]  = {(const float*)d_in[5], (const float*)d_in[7], (const float*)d_in[9]};
    const float* wg[3] = {(const float*)d_in[10], (const float*)d_in[12], (const float*)d_in[14]};
    const float* bg[3] = {(const float*)d_in[11], (const float*)d_in[13], (const float*)d_in[15]};
    float* out = (float*)d_out;

    int N = in_sizes[0] / D;     // 100000
    int E = in_sizes[2] / EF;    // 1250000
    int nblk = (N + SCAN_B - 1) / SCAN_B;   // 98 blocks <= 148 SMs: all resident

    k_edges<<<(E + 255) / 256, 256>>>(ei, ea, aaaaa, E);
    k_scanbuild<<<nblk, SCAN_B>>>(N, nblk, E);

    const int AGG_BLOCKS = 740;   // 148 SMs x 5 blocks: single wave
    // layer 1 (aggpool is launch #4 => ncu capture target)
    k_gemm<<<(N + 127) / 128, 128>>>(x, 0, W[0], N);
    k_aggpool<<<AGG_BLOCKS, 256>>>(1, b[0], wg[0], bg[0], 0, N);
    // layer 2
    k_gemm<<<(N + 127) / 128, 128>>>(x, 1, W[1], N);
    k_aggpool<<<AGG_BLOCKS, 256>>>(2, b[1], wg[1], bg[1], 1, N);
    // layer 3 (pool only)
    k_gemm<<<(N + 127) / 128, 128>>>(x, 2, W[2], N);
    k_aggpool<<<AGG_BLOCKS, 256>>>(0, b[2], wg[2], bg[2], 2, N);

    k_out<<<1, 192>>>(out);
}